// round 16
// baseline (speedup 1.0000x reference)
#include <cuda_runtime.h>
#include <cuda_bf16.h>
#include <cstdint>
#include <math.h>

#define NN 32768
#define XDIM 8
#define LL 16
#define DD 64
#define RR 64
#define HE 256
#define HN 512
#define MX 32
#define LOG2PI_F 1.8378770664093453f
#define PHI_B (NN / 128)

// scratch (device globals: allocation-free contract)
__device__ float g_enc[(size_t)LL * NN * DD];
__device__ float g_XT[(size_t)LL * NN * XDIM];
__device__ float g_tmpAll[LL][(size_t)NN * RR];   // all recurrent states
__device__ float g_res[LL][NN];                   // per-step phi results
__device__ float g_npart[LL * PHI_B];
// update B fragments (plain rn bf16): {b0,b1} per lane
__device__ uint2 g_Bf2[(size_t)(LL - 1) * 256 * 8 * 32];  // [step][kiter256][ntile8][lane]
// phi weight fragments: {b0,b1} per lane
__device__ uint2 g_w1f[4 * 64 * 32];   // stage1: [kc4][ntile64][lane]
__device__ uint2 g_w2f[32 * 8 * 32];   // stage2: [kc32][ntile8][lane]
__device__ uint2 g_hf[68 * 4 * 32];    // head:   [ntile68][kc4][lane]
// encoder weight fragments
__device__ uint32_t g_e1f[32 * 32];    // layer1 (k8): [ntile32][lane]
__device__ uint2 g_e2f[16 * 8 * 32];   // layer2 (k16): [kc16][ntile8][lane]

// ---------------------------------------------------------------- helpers
__device__ __forceinline__ uint32_t pack_rn2(float lo_elem, float hi_elem) {
    uint32_t r;
    asm("cvt.rn.bf16x2.f32 %0, %1, %2;" : "=r"(r) : "f"(hi_elem), "f"(lo_elem));
    return r;
}
__device__ __forceinline__ uint32_t hmul2(uint32_t a, uint32_t b) {
    uint32_t r;
    asm("mul.bf16x2 %0, %1, %2;" : "=r"(r) : "r"(a), "r"(b));
    return r;
}
__device__ __forceinline__ void mma_bf16(float* c,
        uint32_t a0, uint32_t a1, uint32_t a2, uint32_t a3,
        uint32_t b0, uint32_t b1) {
    asm volatile(
        "mma.sync.aligned.m16n8k16.row.col.f32.bf16.bf16.f32 "
        "{%0,%1,%2,%3}, {%4,%5,%6,%7}, {%8,%9}, {%0,%1,%2,%3};"
        : "+f"(c[0]), "+f"(c[1]), "+f"(c[2]), "+f"(c[3])
        : "r"(a0), "r"(a1), "r"(a2), "r"(a3), "r"(b0), "r"(b1));
}
__device__ __forceinline__ void mma_bf16_k8(float* c, uint32_t a0, uint32_t a1, uint32_t b0) {
    asm volatile(
        "mma.sync.aligned.m16n8k8.row.col.f32.bf16.bf16.f32 "
        "{%0,%1,%2,%3}, {%4,%5}, {%6}, {%0,%1,%2,%3};"
        : "+f"(c[0]), "+f"(c[1]), "+f"(c[2]), "+f"(c[3])
        : "r"(a0), "r"(a1), "r"(b0));
}
__device__ __forceinline__ void mma1(float* c, const uint32_t* a, const uint2& bf) {
    mma_bf16(c, a[0], a[1], a[2], a[3], bf.x, bf.y);
}
__device__ __forceinline__ void lse_upd(float& M, float& S, float v) {
    float Mn = fmaxf(M, v);
    S = S * __expf(M - Mn) + __expf(v - Mn);
    M = Mn;
}

// ---------------------------------------------------------------- prep
__global__ void prep_bfrag_kernel(const float* __restrict__ cores) {
    int idx = blockIdx.x * blockDim.x + threadIdx.x;
    if (idx >= (LL - 1) * 256 * 8 * 32) return;
    int lane = idx & 31;
    int nt = (idx >> 5) & 7;
    int ki = (idx >> 8) & 255;
    int l = idx >> 16;
    int g = lane >> 2, tq = lane & 3;
    int n = nt * 8 + g;
    int k0 = ki * 16 + 2 * tq;
    const float* base = cores + (size_t)l * 262144 + (size_t)k0 * 64 + n;
    g_Bf2[idx] = make_uint2(pack_rn2(base[0], base[64]), pack_rn2(base[512], base[576]));
}

__global__ void prep_stage_frags(const float* __restrict__ nw1, const float* __restrict__ nw2,
                                 const float* __restrict__ muw, const float* __restrict__ sgw,
                                 const float* __restrict__ alw,
                                 const float* __restrict__ e1w, const float* __restrict__ e2w) {
    int idx = blockIdx.x * 256 + threadIdx.x;
    if (idx < 8192) {
        int lane = idx & 31, g = lane >> 2, tq = lane & 3;
        int nt = (idx >> 5) & 63;
        int n = nt * 8 + g, k0 = ((idx >> 11) * 16) + 2 * tq;
        const float* w = nw1 + n * RR;
        g_w1f[idx] = make_uint2(pack_rn2(w[k0], w[k0 + 1]), pack_rn2(w[k0 + 8], w[k0 + 9]));
    } else if (idx < 16384) {
        int j = idx - 8192;
        int lane = j & 31, g = lane >> 2, tq = lane & 3;
        int nt = (j >> 5) & 7;
        int n = nt * 8 + g, k0 = ((j >> 8) * 16) + 2 * tq;
        const float* w = nw2 + n * HN;
        g_w2f[j] = make_uint2(pack_rn2(w[k0], w[k0 + 1]), pack_rn2(w[k0 + 8], w[k0 + 9]));
    } else if (idx < 16384 + 8704) {
        int j = idx - 16384;
        int lane = j & 31, g = lane >> 2, tq = lane & 3;
        int kc = (j >> 5) & 3, nt = j >> 7;
        int n = nt * 8 + g, k0 = kc * 16 + 2 * tq;
        const float* w;
        if (n < 512) {
            int m = n >> 4, inner = n & 15;
            w = (inner < 8) ? muw + (m * 8 + inner) * RR : sgw + (m * 8 + inner - 8) * RR;
        } else {
            w = alw + (n - 512) * RR;
        }
        g_hf[j] = make_uint2(pack_rn2(w[k0], w[k0 + 1]), pack_rn2(w[k0 + 8], w[k0 + 9]));
    } else if (idx < 16384 + 8704 + 1024) {
        int j = idx - 16384 - 8704;
        int lane = j & 31, g = lane >> 2, tq = lane & 3;
        int nt = j >> 5;
        int n = nt * 8 + g;
        g_e1f[j] = pack_rn2(e1w[n * XDIM + 2 * tq], e1w[n * XDIM + 2 * tq + 1]);
    } else if (idx < 16384 + 8704 + 1024 + 4096) {
        int j = idx - 16384 - 8704 - 1024;
        int lane = j & 31, g = lane >> 2, tq = lane & 3;
        int nt = (j >> 5) & 7, kc = j >> 8;
        int n = nt * 8 + g, k0 = kc * 16 + 2 * tq;
        const float* w = e2w + n * HE;
        g_e2f[j] = make_uint2(pack_rn2(w[k0], w[k0 + 1]), pack_rn2(w[k0 + 8], w[k0 + 9]));
    }
}

__global__ void init_kernel(const float* __restrict__ iw) {
    int idx = blockIdx.x * blockDim.x + threadIdx.x;
    if (idx < NN * RR) g_tmpAll[0][idx] = iw[idx & (RR - 1)];
}

// ---------------------------------------------------------------- encoder (bf16 mma)
__global__ __launch_bounds__(256) void enc_mma_kernel(const float* __restrict__ X,
        const float* __restrict__ b1e, const float* __restrict__ b2e) {
    __shared__ float sX[128][9];
    int tid = threadIdx.x;
    int wid = tid >> 5, lane = tid & 31;
    int g = lane >> 2, tq = lane & 3;
    int l = blockIdx.x & 15;
    int nb = (blockIdx.x >> 4) * 128;
    int r0 = wid * 16 + g, r1 = r0 + 8;

    for (int v = tid; v < 1024; v += 256) {
        int row = v >> 3, xd = v & 7;
        float x = X[((size_t)(nb + row) * XDIM + xd) * LL + l];
        sX[row][xd] = x;
        g_XT[((size_t)l * NN + nb + row) * XDIM + xd] = x;
    }
    __syncthreads();

    uint32_t a0 = pack_rn2(sX[r0][2 * tq], sX[r0][2 * tq + 1]);
    uint32_t a1 = pack_rn2(sX[r1][2 * tq], sX[r1][2 * tq + 1]);

    float acc2[8][4];
#pragma unroll
    for (int nt = 0; nt < 8; nt++)
#pragma unroll
        for (int c = 0; c < 4; c++) acc2[nt][c] = 0.f;

#pragma unroll
    for (int c = 0; c < 8; c++) {
        float C1[4][4];
#pragma unroll
        for (int nt2 = 0; nt2 < 4; nt2++) {
#pragma unroll
            for (int q = 0; q < 4; q++) C1[nt2][q] = 0.f;
            uint32_t be = __ldg(g_e1f + (c * 4 + nt2) * 32 + lane);
            mma_bf16_k8(C1[nt2], a0, a1, be);
        }
        uint32_t A2[2][4];
#pragma unroll
        for (int j = 0; j < 2; j++) {
            int colA = c * 32 + j * 16 + 2 * tq;
            float ba0 = __ldg(b1e + colA), ba1 = __ldg(b1e + colA + 1);
            float bb0 = __ldg(b1e + colA + 8), bb1 = __ldg(b1e + colA + 9);
            A2[j][0] = pack_rn2(fmaxf(C1[2*j][0] + ba0, 0.f),   fmaxf(C1[2*j][1] + ba1, 0.f));
            A2[j][1] = pack_rn2(fmaxf(C1[2*j][2] + ba0, 0.f),   fmaxf(C1[2*j][3] + ba1, 0.f));
            A2[j][2] = pack_rn2(fmaxf(C1[2*j+1][0] + bb0, 0.f), fmaxf(C1[2*j+1][1] + bb1, 0.f));
            A2[j][3] = pack_rn2(fmaxf(C1[2*j+1][2] + bb0, 0.f), fmaxf(C1[2*j+1][3] + bb1, 0.f));
        }
#pragma unroll
        for (int j = 0; j < 2; j++) {
            int kc = c * 2 + j;
#pragma unroll
            for (int nt = 0; nt < 8; nt++) {
                uint2 bf = __ldg(g_e2f + (kc * 8 + nt) * 32 + lane);
                mma1(acc2[nt], A2[j], bf);
            }
        }
    }

    float* ob = g_enc + ((size_t)l * NN + nb) * DD;
#pragma unroll
    for (int nt = 0; nt < 8; nt++) {
        int col = nt * 8 + 2 * tq;
        float c0 = __ldg(b2e + col), c1 = __ldg(b2e + col + 1);
        *(float2*)(ob + (size_t)r0 * DD + col) = make_float2(acc2[nt][0] + c0, acc2[nt][1] + c1);
        *(float2*)(ob + (size_t)r1 * DD + col) = make_float2(acc2[nt][2] + c0, acc2[nt][3] + c1);
    }
}

// ---------------------------------------------------------------- recurrence update
// 256 rows/CTA, 32 rows/warp (two m16 tiles sharing B fragments). A built via HMUL2 from
// pre-packed bf16 enc registers. grid = NN/256 = 128 (single wave).
// __launch_bounds__(256) — NO min-blocks clause: needs ~160 regs; a 128-reg cap spills.
__global__ __launch_bounds__(256) void update_mma_kernel(int t) {
    __shared__ float sTmp[256][68];
    int tid = threadIdx.x;
    int wid = tid >> 5, lane = tid & 31;
    int g = lane >> 2, tq = lane & 3;
    int sb = blockIdx.x * 256;
    int base = wid * 32;
    int r0 = base + g, r1 = r0 + 8, r2 = r0 + 16, r3 = r0 + 24;

    const float4* tin4 = (const float4*)(g_tmpAll[t - 1] + (size_t)sb * RR);
    for (int v = tid; v < 4096; v += 256) {
        int r = v >> 4, c = (v & 15) << 2;
        *(float4*)&sTmp[r][c] = tin4[v];
    }
    // pre-packed bf16 enc for 4 rows: eb[row][q][2]
    uint32_t eb[4][4][2];
    {
        int rows[4] = {r0, r1, r2, r3};
#pragma unroll
        for (int u = 0; u < 4; u++) {
            const float* ep = g_enc + ((size_t)(t - 1) * NN + sb + rows[u]) * DD;
#pragma unroll
            for (int q = 0; q < 4; q++) {
                float2 a = __ldg((const float2*)(ep + q * 16 + 2 * tq));
                float2 b = __ldg((const float2*)(ep + q * 16 + 2 * tq + 8));
                eb[u][q][0] = pack_rn2(a.x, a.y);
                eb[u][q][1] = pack_rn2(b.x, b.y);
            }
        }
    }
    __syncthreads();

    float acc[2][8][4];
#pragma unroll
    for (int m = 0; m < 2; m++)
#pragma unroll
        for (int nt = 0; nt < 8; nt++)
#pragma unroll
            for (int c = 0; c < 4; c++) acc[m][nt][c] = 0.f;

    const uint2* bfr = g_Bf2 + (size_t)(t - 1) * 65536 + lane;

    for (int i = 0; i < 64; i++) {
        float t0 = sTmp[r0][i], t1 = sTmp[r1][i];
        float t2 = sTmp[r2][i], t3 = sTmp[r3][i];
        uint32_t tb0 = pack_rn2(t0, t0), tb1 = pack_rn2(t1, t1);
        uint32_t tb2 = pack_rn2(t2, t2), tb3 = pack_rn2(t3, t3);
#pragma unroll
        for (int q = 0; q < 4; q++) {
            uint32_t x0 = hmul2(tb0, eb[0][q][0]);
            uint32_t x1 = hmul2(tb1, eb[1][q][0]);
            uint32_t x2 = hmul2(tb0, eb[0][q][1]);
            uint32_t x3 = hmul2(tb1, eb[1][q][1]);
            uint32_t y0 = hmul2(tb2, eb[2][q][0]);
            uint32_t y1 = hmul2(tb3, eb[3][q][0]);
            uint32_t y2 = hmul2(tb2, eb[2][q][1]);
            uint32_t y3 = hmul2(tb3, eb[3][q][1]);
            int ki = (i << 2) + q;
#pragma unroll
            for (int nt = 0; nt < 8; nt++) {
                uint2 bf = __ldg(bfr + (((ki << 3) + nt) << 5));
                mma_bf16(acc[0][nt], x0, x1, x2, x3, bf.x, bf.y);
                mma_bf16(acc[1][nt], y0, y1, y2, y3, bf.x, bf.y);
            }
        }
    }

    float* ob = g_tmpAll[t] + (size_t)sb * RR;
#pragma unroll
    for (int nt = 0; nt < 8; nt++) {
        int col = nt * 8 + 2 * tq;
        *(float2*)(ob + (size_t)r0 * RR + col) = make_float2(acc[0][nt][0], acc[0][nt][1]);
        *(float2*)(ob + (size_t)r1 * RR + col) = make_float2(acc[0][nt][2], acc[0][nt][3]);
        *(float2*)(ob + (size_t)r2 * RR + col) = make_float2(acc[1][nt][0], acc[1][nt][1]);
        *(float2*)(ob + (size_t)r3 * RR + col) = make_float2(acc[1][nt][2], acc[1][nt][3]);
    }
}

// ---------------------------------------------------------------- phi (all 16 steps, bf16 mma chain)
__global__ __launch_bounds__(256) void phi_kernel(
        const float* __restrict__ b1, const float* __restrict__ b2,
        const float* __restrict__ mub, const float* __restrict__ sgb,
        const float* __restrict__ alb) {
    __shared__ float sT[64 * 132];
    __shared__ float sred[256];
    int tid = threadIdx.x;
    int wid = tid >> 5, lane = tid & 31;
    int g = lane >> 2, tq = lane & 3;
    int t = blockIdx.y;
    int bs = blockIdx.x * 128;
    int r0 = wid * 16 + g, r1 = r0 + 8;

    const float4* t4 = (const float4*)(g_tmpAll[t] + (size_t)bs * RR);
    float sq = 0.f;
    for (int v = tid; v < 2048; v += 256) {
        int s = v >> 4, c = (v & 15) << 2;
        float4 a = t4[v];
        sq += a.x * a.x + a.y * a.y + a.z * a.z + a.w * a.w;
        sT[(c + 0) * 132 + s] = a.x; sT[(c + 1) * 132 + s] = a.y;
        sT[(c + 2) * 132 + s] = a.z; sT[(c + 3) * 132 + s] = a.w;
    }
    sred[tid] = sq;
    __syncthreads();
    for (int off = 128; off > 0; off >>= 1) {
        if (tid < off) sred[tid] += sred[tid + off];
        __syncthreads();
    }
    if (tid == 0) g_npart[t * PHI_B + blockIdx.x] = sred[0];

    uint32_t A1[4][4];
#pragma unroll
    for (int ki = 0; ki < 4; ki++) {
        int k0 = ki * 16 + 2 * tq;
        A1[ki][0] = pack_rn2(sT[k0 * 132 + r0], sT[(k0 + 1) * 132 + r0]);
        A1[ki][1] = pack_rn2(sT[k0 * 132 + r1], sT[(k0 + 1) * 132 + r1]);
        A1[ki][2] = pack_rn2(sT[(k0 + 8) * 132 + r0], sT[(k0 + 9) * 132 + r0]);
        A1[ki][3] = pack_rn2(sT[(k0 + 8) * 132 + r1], sT[(k0 + 9) * 132 + r1]);
    }
    __syncthreads();

    float acc2[8][4];
#pragma unroll
    for (int nt = 0; nt < 8; nt++)
#pragma unroll
        for (int c = 0; c < 4; c++) acc2[nt][c] = 0.f;

    for (int c = 0; c < 8; c++) {
        float C1[8][4];
#pragma unroll
        for (int nt2 = 0; nt2 < 8; nt2++) {
#pragma unroll
            for (int q = 0; q < 4; q++) C1[nt2][q] = 0.f;
#pragma unroll
            for (int ki = 0; ki < 4; ki++) {
                uint2 bf = __ldg(g_w1f + (ki * 64 + c * 8 + nt2) * 32 + lane);
                mma1(C1[nt2], A1[ki], bf);
            }
        }
        uint32_t A2[4][4];
#pragma unroll
        for (int j = 0; j < 4; j++) {
            int colA = c * 64 + j * 16 + 2 * tq;
            float ba0 = __ldg(b1 + colA), ba1 = __ldg(b1 + colA + 1);
            float bb0 = __ldg(b1 + colA + 8), bb1 = __ldg(b1 + colA + 9);
            A2[j][0] = pack_rn2(fmaxf(C1[2*j][0] + ba0, 0.f),   fmaxf(C1[2*j][1] + ba1, 0.f));
            A2[j][1] = pack_rn2(fmaxf(C1[2*j][2] + ba0, 0.f),   fmaxf(C1[2*j][3] + ba1, 0.f));
            A2[j][2] = pack_rn2(fmaxf(C1[2*j+1][0] + bb0, 0.f), fmaxf(C1[2*j+1][1] + bb1, 0.f));
            A2[j][3] = pack_rn2(fmaxf(C1[2*j+1][2] + bb0, 0.f), fmaxf(C1[2*j+1][3] + bb1, 0.f));
        }
#pragma unroll
        for (int j = 0; j < 4; j++) {
            int kc = c * 4 + j;
#pragma unroll
            for (int nt = 0; nt < 8; nt++) {
                uint2 bf = __ldg(g_w2f + (kc * 8 + nt) * 32 + lane);
                mma1(acc2[nt], A2[j], bf);
            }
        }
    }

    uint32_t A3[4][4];
#pragma unroll
    for (int j = 0; j < 4; j++) {
        int colA = j * 16 + 2 * tq;
        float ba0 = __ldg(b2 + colA), ba1 = __ldg(b2 + colA + 1);
        float bb0 = __ldg(b2 + colA + 8), bb1 = __ldg(b2 + colA + 9);
        A3[j][0] = pack_rn2(fmaxf(acc2[2*j][0] + ba0, 0.f),   fmaxf(acc2[2*j][1] + ba1, 0.f));
        A3[j][1] = pack_rn2(fmaxf(acc2[2*j][2] + ba0, 0.f),   fmaxf(acc2[2*j][3] + ba1, 0.f));
        A3[j][2] = pack_rn2(fmaxf(acc2[2*j+1][0] + bb0, 0.f), fmaxf(acc2[2*j+1][1] + bb1, 0.f));
        A3[j][3] = pack_rn2(fmaxf(acc2[2*j+1][2] + bb0, 0.f), fmaxf(acc2[2*j+1][3] + bb1, 0.f));
    }

    float alp[4][4];
#pragma unroll
    for (int nt = 0; nt < 4; nt++) {
#pragma unroll
        for (int q = 0; q < 4; q++) alp[nt][q] = 0.f;
#pragma unroll
        for (int kc = 0; kc < 4; kc++) {
            uint2 bf = __ldg(g_hf + ((64 + nt) * 4 + kc) * 32 + lane);
            mma1(alp[nt], A3[kc], bf);
        }
        float a0b = __ldg(alb + nt * 8 + 2 * tq), a1b = __ldg(alb + nt * 8 + 2 * tq + 1);
        alp[nt][0] += a0b; alp[nt][1] += a1b; alp[nt][2] += a0b; alp[nt][3] += a1b;
    }
    float* sAl = sT;
#pragma unroll
    for (int nt = 0; nt < 4; nt++) {
        sAl[r0 * 33 + nt * 8 + 2 * tq]     = alp[nt][0];
        sAl[r0 * 33 + nt * 8 + 2 * tq + 1] = alp[nt][1];
        sAl[r1 * 33 + nt * 8 + 2 * tq]     = alp[nt][2];
        sAl[r1 * 33 + nt * 8 + 2 * tq + 1] = alp[nt][3];
    }
    __syncwarp();

    float Mg = -3.4e38f, Sg = 0.f, Mh = -3.4e38f, Sh = 0.f;
#pragma unroll
    for (int nt = 0; nt < 4; nt++) {
        lse_upd(Mg, Sg, alp[nt][0]); lse_upd(Mg, Sg, alp[nt][1]);
        lse_upd(Mh, Sh, alp[nt][2]); lse_upd(Mh, Sh, alp[nt][3]);
    }
#pragma unroll
    for (int dd = 1; dd < 4; dd <<= 1) {
        float Mo = __shfl_xor_sync(0xffffffffu, Mg, dd);
        float So = __shfl_xor_sync(0xffffffffu, Sg, dd);
        float Mn = fmaxf(Mg, Mo);
        Sg = Sg * __expf(Mg - Mn) + So * __expf(Mo - Mn); Mg = Mn;
        Mo = __shfl_xor_sync(0xffffffffu, Mh, dd);
        So = __shfl_xor_sync(0xffffffffu, Sh, dd);
        Mn = fmaxf(Mh, Mo);
        Sh = Sh * __expf(Mh - Mn) + So * __expf(Mo - Mn); Mh = Mn;
    }

    const float* xp = g_XT + ((size_t)t * NN + bs) * XDIM;
    float2 xa = *(const float2*)(xp + r0 * XDIM + 2 * tq);
    float2 xb = *(const float2*)(xp + r1 * XDIM + 2 * tq);

    float Mtg = -3.4e38f, Stg = 0.f, Mth = -3.4e38f, Sth = 0.f;
#pragma unroll 4
    for (int m = 0; m < 32; m++) {
        float Cm[4] = {0.f, 0.f, 0.f, 0.f}, Cs[4] = {0.f, 0.f, 0.f, 0.f};
#pragma unroll
        for (int kc = 0; kc < 4; kc++) {
            uint2 bm = __ldg(g_hf + ((2 * m) * 4 + kc) * 32 + lane);
            mma1(Cm, A3[kc], bm);
            uint2 bv = __ldg(g_hf + ((2 * m + 1) * 4 + kc) * 32 + lane);
            mma1(Cs, A3[kc], bv);
        }
        float mb0 = __ldg(mub + m * 8 + 2 * tq), mb1 = __ldg(mub + m * 8 + 2 * tq + 1);
        float sb0 = __ldg(sgb + m * 8 + 2 * tq), sb1 = __ldg(sgb + m * 8 + 2 * tq + 1);
        float l0 = Cs[0] + sb0, l1 = Cs[1] + sb1, l2 = Cs[2] + sb0, l3 = Cs[3] + sb1;
        float z0 = (xa.x - (Cm[0] + mb0)) * __expf(-l0);
        float z1 = (xa.y - (Cm[1] + mb1)) * __expf(-l1);
        float z2 = (xb.x - (Cm[2] + mb0)) * __expf(-l2);
        float z3 = (xb.y - (Cm[3] + mb1)) * __expf(-l3);
        float cg = -0.5f * z0 * z0 - l0 - 0.5f * z1 * z1 - l1;
        float ch = -0.5f * z2 * z2 - l2 - 0.5f * z3 * z3 - l3;
        cg += __shfl_xor_sync(0xffffffffu, cg, 1);
        cg += __shfl_xor_sync(0xffffffffu, cg, 2);
        ch += __shfl_xor_sync(0xffffffffu, ch, 1);
        ch += __shfl_xor_sync(0xffffffffu, ch, 2);
        cg += -0.5f * XDIM * LOG2PI_F;
        ch += -0.5f * XDIM * LOG2PI_F;
        float ag = sAl[r0 * 33 + m], ah = sAl[r1 * 33 + m];
        lse_upd(Mtg, Stg, ag + cg);
        lse_upd(Mth, Sth, ah + ch);
    }
    if (tq == 0) {
        g_res[t][bs + r0] = (Mtg + __logf(Stg)) - (Mg + __logf(Sg));
        g_res[t][bs + r1] = (Mth + __logf(Sth)) - (Mh + __logf(Sh));
    }
}

// ---------------------------------------------------------------- finish
__global__ void finish_kernel(float* __restrict__ out, int out_n) {
    int idx = blockIdx.x * 256 + threadIdx.x;
    if (idx < NN) {
        float s = 0.f;
#pragma unroll
        for (int t = 0; t < LL; t++) s += g_res[t][idx];
        out[idx] = s;
    } else if (idx < out_n) {
        out[idx] = 0.f;
    }
}

__global__ void norm_kernel(float* __restrict__ out, int out_n) {
    __shared__ float red[256];
    int tid = threadIdx.x;
    float s = 0.f;
    for (int v = tid; v < LL * PHI_B; v += 256) s += g_npart[v];
    red[tid] = s;
    __syncthreads();
    for (int off = 128; off > 0; off >>= 1) {
        if (tid < off) red[tid] += red[tid + off];
        __syncthreads();
    }
    if (tid == 0) out[out_n - 1] = red[0];
}

// ---------------------------------------------------------------- launch
extern "C" void kernel_launch(void* const* d_in, const int* in_sizes, int n_in,
                              void* d_out, int out_size) {
    const float* X    = (const float*)d_in[0];
    const float* iw   = (const float*)d_in[1];
    const float* cores= (const float*)d_in[2];
    const float* e1w  = (const float*)d_in[3];
    const float* e1b  = (const float*)d_in[4];
    const float* e2w  = (const float*)d_in[5];
    const float* e2b  = (const float*)d_in[6];
    const float* nw1  = (const float*)d_in[7];
    const float* nb1  = (const float*)d_in[8];
    const float* nw2  = (const float*)d_in[9];
    const float* nb2  = (const float*)d_in[10];
    const float* muw  = (const float*)d_in[11];
    const float* mub  = (const float*)d_in[12];
    const float* sgw  = (const float*)d_in[13];
    const float* sgb  = (const float*)d_in[14];
    const float* alw  = (const float*)d_in[15];
    const float* alb  = (const float*)d_in[16];
    float* out = (float*)d_out;

    prep_bfrag_kernel<<<((LL - 1) * 256 * 8 * 32 + 255) / 256, 256>>>(cores);
    prep_stage_frags<<<(16384 + 8704 + 1024 + 4096 + 255) / 256, 256>>>(nw1, nw2, muw, sgw, alw, e1w, e2w);
    init_kernel<<<(NN * RR + 255) / 256, 256>>>(iw);
    enc_mma_kernel<<<(LL * NN) / 128, 256>>>(X, e1b, e2b);

    for (int t = 1; t < LL; t++)
        update_mma_kernel<<<NN / 256, 256>>>(t);

    dim3 pg(PHI_B, LL);
    phi_kernel<<<pg, 256>>>(nb1, nb2, mub, sgb, alb);

    finish_kernel<<<(out_size + 255) / 256, 256>>>(out, out_size);
    norm_kernel<<<1, 256>>>(out, out_size);
}

// round 17
// speedup vs baseline: 2.1462x; 2.1462x over previous
#include <cuda_runtime.h>
#include <cuda_bf16.h>
#include <cstdint>
#include <math.h>

#define NN 32768
#define XDIM 8
#define LL 16
#define DD 64
#define RR 64
#define HE 256
#define HN 512
#define MX 32
#define LOG2PI_F 1.8378770664093453f
#define PHI_B (NN / 128)

// scratch (device globals: allocation-free contract)
__device__ float g_enc[(size_t)LL * NN * DD];
__device__ float g_XT[(size_t)LL * NN * XDIM];
__device__ float g_tmpAll[LL][(size_t)NN * RR];   // all recurrent states
__device__ float g_res[LL][NN];                   // per-step phi results
__device__ float g_npart[LL * PHI_B];
// update B fragments, paired n-tiles: uint4 {nt0.b0, nt0.b1, nt1.b0, nt1.b1} per lane
__device__ uint4 g_Bf4[(size_t)(LL - 1) * 256 * 4 * 32];  // [step][kiter256][ntpair4][lane]
// phi weight fragments: {b0,b1} per lane
__device__ uint2 g_w1f[4 * 64 * 32];   // stage1: [kc4][ntile64][lane]
__device__ uint2 g_w2f[32 * 8 * 32];   // stage2: [kc32][ntile8][lane]
__device__ uint2 g_hf[68 * 4 * 32];    // head:   [ntile68][kc4][lane]
// encoder weight fragments
__device__ uint32_t g_e1f[32 * 32];    // layer1 (k8): [ntile32][lane]
__device__ uint2 g_e2f[16 * 8 * 32];   // layer2 (k16): [kc16][ntile8][lane]

// ---------------------------------------------------------------- helpers
__device__ __forceinline__ uint32_t pack_rn2(float lo_elem, float hi_elem) {
    uint32_t r;
    asm("cvt.rn.bf16x2.f32 %0, %1, %2;" : "=r"(r) : "f"(hi_elem), "f"(lo_elem));
    return r;
}
__device__ __forceinline__ uint32_t hmul2(uint32_t a, uint32_t b) {
    uint32_t r;
    asm("mul.bf16x2 %0, %1, %2;" : "=r"(r) : "r"(a), "r"(b));
    return r;
}
__device__ __forceinline__ void mma_bf16(float* c,
        uint32_t a0, uint32_t a1, uint32_t a2, uint32_t a3,
        uint32_t b0, uint32_t b1) {
    asm volatile(
        "mma.sync.aligned.m16n8k16.row.col.f32.bf16.bf16.f32 "
        "{%0,%1,%2,%3}, {%4,%5,%6,%7}, {%8,%9}, {%0,%1,%2,%3};"
        : "+f"(c[0]), "+f"(c[1]), "+f"(c[2]), "+f"(c[3])
        : "r"(a0), "r"(a1), "r"(a2), "r"(a3), "r"(b0), "r"(b1));
}
__device__ __forceinline__ void mma_bf16_k8(float* c, uint32_t a0, uint32_t a1, uint32_t b0) {
    asm volatile(
        "mma.sync.aligned.m16n8k8.row.col.f32.bf16.bf16.f32 "
        "{%0,%1,%2,%3}, {%4,%5}, {%6}, {%0,%1,%2,%3};"
        : "+f"(c[0]), "+f"(c[1]), "+f"(c[2]), "+f"(c[3])
        : "r"(a0), "r"(a1), "r"(b0));
}
__device__ __forceinline__ void mma1(float* c, const uint32_t* a, const uint2& bf) {
    mma_bf16(c, a[0], a[1], a[2], a[3], bf.x, bf.y);
}
__device__ __forceinline__ void lse_upd(float& M, float& S, float v) {
    float Mn = fmaxf(M, v);
    S = S * __expf(M - Mn) + __expf(v - Mn);
    M = Mn;
}

// ---------------------------------------------------------------- prep
// B fragments, n-tile pairs: lane covers n0 = ntp*16 + g (frag .x/.y) and n1 = n0+8 (.z/.w)
__global__ void prep_bfrag_kernel(const float* __restrict__ cores) {
    int idx = blockIdx.x * blockDim.x + threadIdx.x;
    if (idx >= (LL - 1) * 256 * 4 * 32) return;
    int lane = idx & 31;
    int ntp = (idx >> 5) & 3;
    int ki = (idx >> 7) & 255;
    int l = idx >> 15;
    int g = lane >> 2, tq = lane & 3;
    int n0 = ntp * 16 + g;
    int k0 = ki * 16 + 2 * tq;
    const float* base = cores + (size_t)l * 262144 + (size_t)k0 * 64;
    uint4 r;
    r.x = pack_rn2(base[n0],       base[64 + n0]);
    r.y = pack_rn2(base[512 + n0], base[576 + n0]);
    r.z = pack_rn2(base[n0 + 8],       base[64 + n0 + 8]);
    r.w = pack_rn2(base[512 + n0 + 8], base[576 + n0 + 8]);
    g_Bf4[idx] = r;
}

__global__ void prep_stage_frags(const float* __restrict__ nw1, const float* __restrict__ nw2,
                                 const float* __restrict__ muw, const float* __restrict__ sgw,
                                 const float* __restrict__ alw,
                                 const float* __restrict__ e1w, const float* __restrict__ e2w) {
    int idx = blockIdx.x * 256 + threadIdx.x;
    if (idx < 8192) {
        int lane = idx & 31, g = lane >> 2, tq = lane & 3;
        int nt = (idx >> 5) & 63;
        int n = nt * 8 + g, k0 = ((idx >> 11) * 16) + 2 * tq;
        const float* w = nw1 + n * RR;
        g_w1f[idx] = make_uint2(pack_rn2(w[k0], w[k0 + 1]), pack_rn2(w[k0 + 8], w[k0 + 9]));
    } else if (idx < 16384) {
        int j = idx - 8192;
        int lane = j & 31, g = lane >> 2, tq = lane & 3;
        int nt = (j >> 5) & 7;
        int n = nt * 8 + g, k0 = ((j >> 8) * 16) + 2 * tq;
        const float* w = nw2 + n * HN;
        g_w2f[j] = make_uint2(pack_rn2(w[k0], w[k0 + 1]), pack_rn2(w[k0 + 8], w[k0 + 9]));
    } else if (idx < 16384 + 8704) {
        int j = idx - 16384;
        int lane = j & 31, g = lane >> 2, tq = lane & 3;
        int kc = (j >> 5) & 3, nt = j >> 7;
        int n = nt * 8 + g, k0 = kc * 16 + 2 * tq;
        const float* w;
        if (n < 512) {
            int m = n >> 4, inner = n & 15;
            w = (inner < 8) ? muw + (m * 8 + inner) * RR : sgw + (m * 8 + inner - 8) * RR;
        } else {
            w = alw + (n - 512) * RR;
        }
        g_hf[j] = make_uint2(pack_rn2(w[k0], w[k0 + 1]), pack_rn2(w[k0 + 8], w[k0 + 9]));
    } else if (idx < 16384 + 8704 + 1024) {
        int j = idx - 16384 - 8704;
        int lane = j & 31, g = lane >> 2, tq = lane & 3;
        int nt = j >> 5;
        int n = nt * 8 + g;
        g_e1f[j] = pack_rn2(e1w[n * XDIM + 2 * tq], e1w[n * XDIM + 2 * tq + 1]);
    } else if (idx < 16384 + 8704 + 1024 + 4096) {
        int j = idx - 16384 - 8704 - 1024;
        int lane = j & 31, g = lane >> 2, tq = lane & 3;
        int nt = (j >> 5) & 7, kc = j >> 8;
        int n = nt * 8 + g, k0 = kc * 16 + 2 * tq;
        const float* w = e2w + n * HE;
        g_e2f[j] = make_uint2(pack_rn2(w[k0], w[k0 + 1]), pack_rn2(w[k0 + 8], w[k0 + 9]));
    }
}

__global__ void init_kernel(const float* __restrict__ iw) {
    int idx = blockIdx.x * blockDim.x + threadIdx.x;
    if (idx < NN * RR) g_tmpAll[0][idx] = iw[idx & (RR - 1)];
}

// ---------------------------------------------------------------- encoder (bf16 mma)
__global__ __launch_bounds__(256) void enc_mma_kernel(const float* __restrict__ X,
        const float* __restrict__ b1e, const float* __restrict__ b2e) {
    __shared__ float sX[128][9];
    int tid = threadIdx.x;
    int wid = tid >> 5, lane = tid & 31;
    int g = lane >> 2, tq = lane & 3;
    int l = blockIdx.x & 15;
    int nb = (blockIdx.x >> 4) * 128;
    int r0 = wid * 16 + g, r1 = r0 + 8;

    for (int v = tid; v < 1024; v += 256) {
        int row = v >> 3, xd = v & 7;
        float x = X[((size_t)(nb + row) * XDIM + xd) * LL + l];
        sX[row][xd] = x;
        g_XT[((size_t)l * NN + nb + row) * XDIM + xd] = x;
    }
    __syncthreads();

    uint32_t a0 = pack_rn2(sX[r0][2 * tq], sX[r0][2 * tq + 1]);
    uint32_t a1 = pack_rn2(sX[r1][2 * tq], sX[r1][2 * tq + 1]);

    float acc2[8][4];
#pragma unroll
    for (int nt = 0; nt < 8; nt++)
#pragma unroll
        for (int c = 0; c < 4; c++) acc2[nt][c] = 0.f;

#pragma unroll
    for (int c = 0; c < 8; c++) {
        float C1[4][4];
#pragma unroll
        for (int nt2 = 0; nt2 < 4; nt2++) {
#pragma unroll
            for (int q = 0; q < 4; q++) C1[nt2][q] = 0.f;
            uint32_t be = __ldg(g_e1f + (c * 4 + nt2) * 32 + lane);
            mma_bf16_k8(C1[nt2], a0, a1, be);
        }
        uint32_t A2[2][4];
#pragma unroll
        for (int j = 0; j < 2; j++) {
            int colA = c * 32 + j * 16 + 2 * tq;
            float ba0 = __ldg(b1e + colA), ba1 = __ldg(b1e + colA + 1);
            float bb0 = __ldg(b1e + colA + 8), bb1 = __ldg(b1e + colA + 9);
            A2[j][0] = pack_rn2(fmaxf(C1[2*j][0] + ba0, 0.f),   fmaxf(C1[2*j][1] + ba1, 0.f));
            A2[j][1] = pack_rn2(fmaxf(C1[2*j][2] + ba0, 0.f),   fmaxf(C1[2*j][3] + ba1, 0.f));
            A2[j][2] = pack_rn2(fmaxf(C1[2*j+1][0] + bb0, 0.f), fmaxf(C1[2*j+1][1] + bb1, 0.f));
            A2[j][3] = pack_rn2(fmaxf(C1[2*j+1][2] + bb0, 0.f), fmaxf(C1[2*j+1][3] + bb1, 0.f));
        }
#pragma unroll
        for (int j = 0; j < 2; j++) {
            int kc = c * 2 + j;
#pragma unroll
            for (int nt = 0; nt < 8; nt++) {
                uint2 bf = __ldg(g_e2f + (kc * 8 + nt) * 32 + lane);
                mma1(acc2[nt], A2[j], bf);
            }
        }
    }

    float* ob = g_enc + ((size_t)l * NN + nb) * DD;
#pragma unroll
    for (int nt = 0; nt < 8; nt++) {
        int col = nt * 8 + 2 * tq;
        float c0 = __ldg(b2e + col), c1 = __ldg(b2e + col + 1);
        *(float2*)(ob + (size_t)r0 * DD + col) = make_float2(acc2[nt][0] + c0, acc2[nt][1] + c1);
        *(float2*)(ob + (size_t)r1 * DD + col) = make_float2(acc2[nt][2] + c0, acc2[nt][3] + c1);
    }
}

// ---------------------------------------------------------------- recurrence update
// R13 occupancy envelope: 128 rows/CTA, 16 rows/warp, (256,2), grid NN/128 = 256.
// Leaner inner loop: HMUL2 A-build from pre-packed bf16 enc + uint4 paired B loads.
__global__ __launch_bounds__(256, 2) void update_mma_kernel(int t) {
    __shared__ float sTmp[128][68];
    int tid = threadIdx.x;
    int wid = tid >> 5, lane = tid & 31;
    int g = lane >> 2, tq = lane & 3;
    int sb = blockIdx.x * 128;
    int r0 = wid * 16 + g, r1 = r0 + 8;

    const float4* tin4 = (const float4*)(g_tmpAll[t - 1] + (size_t)sb * RR);
    for (int v = tid; v < 2048; v += 256) {
        int r = v >> 4, c = (v & 15) << 2;
        *(float4*)&sTmp[r][c] = tin4[v];
    }
    // pre-packed bf16 enc for rows r0, r1: eb[row][q][half]
    uint32_t eb[2][4][2];
    {
        int rows[2] = {r0, r1};
#pragma unroll
        for (int u = 0; u < 2; u++) {
            const float* ep = g_enc + ((size_t)(t - 1) * NN + sb + rows[u]) * DD;
#pragma unroll
            for (int q = 0; q < 4; q++) {
                float2 a = __ldg((const float2*)(ep + q * 16 + 2 * tq));
                float2 b = __ldg((const float2*)(ep + q * 16 + 2 * tq + 8));
                eb[u][q][0] = pack_rn2(a.x, a.y);
                eb[u][q][1] = pack_rn2(b.x, b.y);
            }
        }
    }
    __syncthreads();

    float acc[8][4];
#pragma unroll
    for (int nt = 0; nt < 8; nt++)
#pragma unroll
        for (int c = 0; c < 4; c++) acc[nt][c] = 0.f;

    const uint4* bfr = g_Bf4 + (size_t)(t - 1) * 32768 + lane;

    for (int i = 0; i < 64; i++) {
        float t0 = sTmp[r0][i], t1 = sTmp[r1][i];
        uint32_t tb0 = pack_rn2(t0, t0), tb1 = pack_rn2(t1, t1);
#pragma unroll
        for (int q = 0; q < 4; q++) {
            uint32_t a0 = hmul2(tb0, eb[0][q][0]);
            uint32_t a1 = hmul2(tb1, eb[1][q][0]);
            uint32_t a2 = hmul2(tb0, eb[0][q][1]);
            uint32_t a3 = hmul2(tb1, eb[1][q][1]);
            int ki = (i << 2) + q;
#pragma unroll
            for (int ntp = 0; ntp < 4; ntp++) {
                uint4 bf = __ldg(bfr + (((ki << 2) + ntp) << 5));
                mma_bf16(acc[2 * ntp],     a0, a1, a2, a3, bf.x, bf.y);
                mma_bf16(acc[2 * ntp + 1], a0, a1, a2, a3, bf.z, bf.w);
            }
        }
    }

    float* ob = g_tmpAll[t] + (size_t)sb * RR;
#pragma unroll
    for (int nt = 0; nt < 8; nt++) {
        int col = nt * 8 + 2 * tq;
        *(float2*)(ob + (size_t)r0 * RR + col) = make_float2(acc[nt][0], acc[nt][1]);
        *(float2*)(ob + (size_t)r1 * RR + col) = make_float2(acc[nt][2], acc[nt][3]);
    }
}

// ---------------------------------------------------------------- phi (all 16 steps, bf16 mma chain)
__global__ __launch_bounds__(256) void phi_kernel(
        const float* __restrict__ b1, const float* __restrict__ b2,
        const float* __restrict__ mub, const float* __restrict__ sgb,
        const float* __restrict__ alb) {
    __shared__ float sT[64 * 132];
    __shared__ float sred[256];
    int tid = threadIdx.x;
    int wid = tid >> 5, lane = tid & 31;
    int g = lane >> 2, tq = lane & 3;
    int t = blockIdx.y;
    int bs = blockIdx.x * 128;
    int r0 = wid * 16 + g, r1 = r0 + 8;

    const float4* t4 = (const float4*)(g_tmpAll[t] + (size_t)bs * RR);
    float sq = 0.f;
    for (int v = tid; v < 2048; v += 256) {
        int s = v >> 4, c = (v & 15) << 2;
        float4 a = t4[v];
        sq += a.x * a.x + a.y * a.y + a.z * a.z + a.w * a.w;
        sT[(c + 0) * 132 + s] = a.x; sT[(c + 1) * 132 + s] = a.y;
        sT[(c + 2) * 132 + s] = a.z; sT[(c + 3) * 132 + s] = a.w;
    }
    sred[tid] = sq;
    __syncthreads();
    for (int off = 128; off > 0; off >>= 1) {
        if (tid < off) sred[tid] += sred[tid + off];
        __syncthreads();
    }
    if (tid == 0) g_npart[t * PHI_B + blockIdx.x] = sred[0];

    uint32_t A1[4][4];
#pragma unroll
    for (int ki = 0; ki < 4; ki++) {
        int k0 = ki * 16 + 2 * tq;
        A1[ki][0] = pack_rn2(sT[k0 * 132 + r0], sT[(k0 + 1) * 132 + r0]);
        A1[ki][1] = pack_rn2(sT[k0 * 132 + r1], sT[(k0 + 1) * 132 + r1]);
        A1[ki][2] = pack_rn2(sT[(k0 + 8) * 132 + r0], sT[(k0 + 9) * 132 + r0]);
        A1[ki][3] = pack_rn2(sT[(k0 + 8) * 132 + r1], sT[(k0 + 9) * 132 + r1]);
    }
    __syncthreads();

    float acc2[8][4];
#pragma unroll
    for (int nt = 0; nt < 8; nt++)
#pragma unroll
        for (int c = 0; c < 4; c++) acc2[nt][c] = 0.f;

    for (int c = 0; c < 8; c++) {
        float C1[8][4];
#pragma unroll
        for (int nt2 = 0; nt2 < 8; nt2++) {
#pragma unroll
            for (int q = 0; q < 4; q++) C1[nt2][q] = 0.f;
#pragma unroll
            for (int ki = 0; ki < 4; ki++) {
                uint2 bf = __ldg(g_w1f + (ki * 64 + c * 8 + nt2) * 32 + lane);
                mma1(C1[nt2], A1[ki], bf);
            }
        }
        uint32_t A2[4][4];
#pragma unroll
        for (int j = 0; j < 4; j++) {
            int colA = c * 64 + j * 16 + 2 * tq;
            float ba0 = __ldg(b1 + colA), ba1 = __ldg(b1 + colA + 1);
            float bb0 = __ldg(b1 + colA + 8), bb1 = __ldg(b1 + colA + 9);
            A2[j][0] = pack_rn2(fmaxf(C1[2*j][0] + ba0, 0.f),   fmaxf(C1[2*j][1] + ba1, 0.f));
            A2[j][1] = pack_rn2(fmaxf(C1[2*j][2] + ba0, 0.f),   fmaxf(C1[2*j][3] + ba1, 0.f));
            A2[j][2] = pack_rn2(fmaxf(C1[2*j+1][0] + bb0, 0.f), fmaxf(C1[2*j+1][1] + bb1, 0.f));
            A2[j][3] = pack_rn2(fmaxf(C1[2*j+1][2] + bb0, 0.f), fmaxf(C1[2*j+1][3] + bb1, 0.f));
        }
#pragma unroll
        for (int j = 0; j < 4; j++) {
            int kc = c * 4 + j;
#pragma unroll
            for (int nt = 0; nt < 8; nt++) {
                uint2 bf = __ldg(g_w2f + (kc * 8 + nt) * 32 + lane);
                mma1(acc2[nt], A2[j], bf);
            }
        }
    }

    uint32_t A3[4][4];
#pragma unroll
    for (int j = 0; j < 4; j++) {
        int colA = j * 16 + 2 * tq;
        float ba0 = __ldg(b2 + colA), ba1 = __ldg(b2 + colA + 1);
        float bb0 = __ldg(b2 + colA + 8), bb1 = __ldg(b2 + colA + 9);
        A3[j][0] = pack_rn2(fmaxf(acc2[2*j][0] + ba0, 0.f),   fmaxf(acc2[2*j][1] + ba1, 0.f));
        A3[j][1] = pack_rn2(fmaxf(acc2[2*j][2] + ba0, 0.f),   fmaxf(acc2[2*j][3] + ba1, 0.f));
        A3[j][2] = pack_rn2(fmaxf(acc2[2*j+1][0] + bb0, 0.f), fmaxf(acc2[2*j+1][1] + bb1, 0.f));
        A3[j][3] = pack_rn2(fmaxf(acc2[2*j+1][2] + bb0, 0.f), fmaxf(acc2[2*j+1][3] + bb1, 0.f));
    }

    float alp[4][4];
#pragma unroll
    for (int nt = 0; nt < 4; nt++) {
#pragma unroll
        for (int q = 0; q < 4; q++) alp[nt][q] = 0.f;
#pragma unroll
        for (int kc = 0; kc < 4; kc++) {
            uint2 bf = __ldg(g_hf + ((64 + nt) * 4 + kc) * 32 + lane);
            mma1(alp[nt], A3[kc], bf);
        }
        float a0b = __ldg(alb + nt * 8 + 2 * tq), a1b = __ldg(alb + nt * 8 + 2 * tq + 1);
        alp[nt][0] += a0b; alp[nt][1] += a1b; alp[nt][2] += a0b; alp[nt][3] += a1b;
    }
    float* sAl = sT;
#pragma unroll
    for (int nt = 0; nt < 4; nt++) {
        sAl[r0 * 33 + nt * 8 + 2 * tq]     = alp[nt][0];
        sAl[r0 * 33 + nt * 8 + 2 * tq + 1] = alp[nt][1];
        sAl[r1 * 33 + nt * 8 + 2 * tq]     = alp[nt][2];
        sAl[r1 * 33 + nt * 8 + 2 * tq + 1] = alp[nt][3];
    }
    __syncwarp();

    float Mg = -3.4e38f, Sg = 0.f, Mh = -3.4e38f, Sh = 0.f;
#pragma unroll
    for (int nt = 0; nt < 4; nt++) {
        lse_upd(Mg, Sg, alp[nt][0]); lse_upd(Mg, Sg, alp[nt][1]);
        lse_upd(Mh, Sh, alp[nt][2]); lse_upd(Mh, Sh, alp[nt][3]);
    }
#pragma unroll
    for (int dd = 1; dd < 4; dd <<= 1) {
        float Mo = __shfl_xor_sync(0xffffffffu, Mg, dd);
        float So = __shfl_xor_sync(0xffffffffu, Sg, dd);
        float Mn = fmaxf(Mg, Mo);
        Sg = Sg * __expf(Mg - Mn) + So * __expf(Mo - Mn); Mg = Mn;
        Mo = __shfl_xor_sync(0xffffffffu, Mh, dd);
        So = __shfl_xor_sync(0xffffffffu, Sh, dd);
        Mn = fmaxf(Mh, Mo);
        Sh = Sh * __expf(Mh - Mn) + So * __expf(Mo - Mn); Mh = Mn;
    }

    const float* xp = g_XT + ((size_t)t * NN + bs) * XDIM;
    float2 xa = *(const float2*)(xp + r0 * XDIM + 2 * tq);
    float2 xb = *(const float2*)(xp + r1 * XDIM + 2 * tq);

    float Mtg = -3.4e38f, Stg = 0.f, Mth = -3.4e38f, Sth = 0.f;
#pragma unroll 4
    for (int m = 0; m < 32; m++) {
        float Cm[4] = {0.f, 0.f, 0.f, 0.f}, Cs[4] = {0.f, 0.f, 0.f, 0.f};
#pragma unroll
        for (int kc = 0; kc < 4; kc++) {
            uint2 bm = __ldg(g_hf + ((2 * m) * 4 + kc) * 32 + lane);
            mma1(Cm, A3[kc], bm);
            uint2 bv = __ldg(g_hf + ((2 * m + 1) * 4 + kc) * 32 + lane);
            mma1(Cs, A3[kc], bv);
        }
        float mb0 = __ldg(mub + m * 8 + 2 * tq), mb1 = __ldg(mub + m * 8 + 2 * tq + 1);
        float sb0 = __ldg(sgb + m * 8 + 2 * tq), sb1 = __ldg(sgb + m * 8 + 2 * tq + 1);
        float l0 = Cs[0] + sb0, l1 = Cs[1] + sb1, l2 = Cs[2] + sb0, l3 = Cs[3] + sb1;
        float z0 = (xa.x - (Cm[0] + mb0)) * __expf(-l0);
        float z1 = (xa.y - (Cm[1] + mb1)) * __expf(-l1);
        float z2 = (xb.x - (Cm[2] + mb0)) * __expf(-l2);
        float z3 = (xb.y - (Cm[3] + mb1)) * __expf(-l3);
        float cg = -0.5f * z0 * z0 - l0 - 0.5f * z1 * z1 - l1;
        float ch = -0.5f * z2 * z2 - l2 - 0.5f * z3 * z3 - l3;
        cg += __shfl_xor_sync(0xffffffffu, cg, 1);
        cg += __shfl_xor_sync(0xffffffffu, cg, 2);
        ch += __shfl_xor_sync(0xffffffffu, ch, 1);
        ch += __shfl_xor_sync(0xffffffffu, ch, 2);
        cg += -0.5f * XDIM * LOG2PI_F;
        ch += -0.5f * XDIM * LOG2PI_F;
        float ag = sAl[r0 * 33 + m], ah = sAl[r1 * 33 + m];
        lse_upd(Mtg, Stg, ag + cg);
        lse_upd(Mth, Sth, ah + ch);
    }
    if (tq == 0) {
        g_res[t][bs + r0] = (Mtg + __logf(Stg)) - (Mg + __logf(Sg));
        g_res[t][bs + r1] = (Mth + __logf(Sth)) - (Mh + __logf(Sh));
    }
}

// ---------------------------------------------------------------- finish
__global__ void finish_kernel(float* __restrict__ out, int out_n) {
    int idx = blockIdx.x * 256 + threadIdx.x;
    if (idx < NN) {
        float s = 0.f;
#pragma unroll
        for (int t = 0; t < LL; t++) s += g_res[t][idx];
        out[idx] = s;
    } else if (idx < out_n) {
        out[idx] = 0.f;
    }
}

__global__ void norm_kernel(float* __restrict__ out, int out_n) {
    __shared__ float red[256];
    int tid = threadIdx.x;
    float s = 0.f;
    for (int v = tid; v < LL * PHI_B; v += 256) s += g_npart[v];
    red[tid] = s;
    __syncthreads();
    for (int off = 128; off > 0; off >>= 1) {
        if (tid < off) red[tid] += red[tid + off];
        __syncthreads();
    }
    if (tid == 0) out[out_n - 1] = red[0];
}

// ---------------------------------------------------------------- launch
extern "C" void kernel_launch(void* const* d_in, const int* in_sizes, int n_in,
                              void* d_out, int out_size) {
    const float* X    = (const float*)d_in[0];
    const float* iw   = (const float*)d_in[1];
    const float* cores= (const float*)d_in[2];
    const float* e1w  = (const float*)d_in[3];
    const float* e1b  = (const float*)d_in[4];
    const float* e2w  = (const float*)d_in[5];
    const float* e2b  = (const float*)d_in[6];
    const float* nw1  = (const float*)d_in[7];
    const float* nb1  = (const float*)d_in[8];
    const float* nw2  = (const float*)d_in[9];
    const float* nb2  = (const float*)d_in[10];
    const float* muw  = (const float*)d_in[11];
    const float* mub  = (const float*)d_in[12];
    const float* sgw  = (const float*)d_in[13];
    const float* sgb  = (const float*)d_in[14];
    const float* alw  = (const float*)d_in[15];
    const float* alb  = (const float*)d_in[16];
    float* out = (float*)d_out;

    prep_bfrag_kernel<<<((LL - 1) * 256 * 4 * 32 + 255) / 256, 256>>>(cores);
    prep_stage_frags<<<(16384 + 8704 + 1024 + 4096 + 255) / 256, 256>>>(nw1, nw2, muw, sgw, alw, e1w, e2w);
    init_kernel<<<(NN * RR + 255) / 256, 256>>>(iw);
    enc_mma_kernel<<<(LL * NN) / 128, 256>>>(X, e1b, e2b);

    for (int t = 1; t < LL; t++)
        update_mma_kernel<<<NN / 128, 256>>>(t);

    dim3 pg(PHI_B, LL);
    phi_kernel<<<pg, 256>>>(nb1, nb2, mub, sgb, alb);

    finish_kernel<<<(out_size + 255) / 256, 256>>>(out, out_size);
    norm_kernel<<<1, 256>>>(out, out_size);
}